// round 8
// baseline (speedup 1.0000x reference)
#include <cuda_runtime.h>
#include <cuda_bf16.h>

// Fused GenderAwareCrossEntropyLoss.
// ALL inputs (logits+labels+gender) staged via cp.async, ring-3, prefetch depth 2.
// d_in[0] logits f32 [N,7]; d_in[1] class_weights f32 [7];
// d_in[2] labels i32 [N];  d_in[3] gender i32 [N,2].
// d_out f32[1] = mean(weighted CE + gender penalty).

#define NCLS 7
#define BLOCK 512
#define TILE_ROWS 512
#define TILE_FLOATS (TILE_ROWS * NCLS)   // 3584
#define TILE_F4 (TILE_FLOATS / 4)        // 896 logits float4 per tile
#define LAB_F4 (TILE_ROWS / 4)           // 128 label float4 per tile
#define GEN_F4 (TILE_ROWS / 2)           // 256 gender float4 per tile
#define GRID_BLOCKS (148 * 3)

struct Tile {                             // packed: 14336 + 2048 + 4096 = 20480 B
    float lg[TILE_FLOATS];
    int   lab[TILE_ROWS];
    int2  gen[TILE_ROWS];
};

__device__ double       g_accum = 0.0;
__device__ unsigned int g_count = 0u;

__device__ __forceinline__ unsigned smem_u32(const void* p) {
    return (unsigned)__cvta_generic_to_shared(p);
}
__device__ __forceinline__ void cp16(unsigned dst, const void* src) {
    asm volatile("cp.async.cg.shared.global [%0], [%1], 16;\n" :: "r"(dst), "l"(src));
}
__device__ __forceinline__ void cp_commit() {
    asm volatile("cp.async.commit_group;\n" ::: "memory");
}
template <int N>
__device__ __forceinline__ void cp_wait() {
    asm volatile("cp.async.wait_group %0;\n" :: "n"(N) : "memory");
}

__global__ void __launch_bounds__(BLOCK, 3)
gender_ce_kernel(const float* __restrict__ logits,
                 const float* __restrict__ cw,
                 const int*   __restrict__ labels,
                 const int*   __restrict__ gender,
                 float* __restrict__ out,
                 int nrows)
{
    extern __shared__ __align__(16) char smem_raw[];
    Tile* tiles = reinterpret_cast<Tile*>(smem_raw);     // 3 buffers
    __shared__ float scw[8];

    const int t          = threadIdx.x;
    const int G          = gridDim.x;
    const int nTiles     = (nrows + TILE_ROWS - 1) / TILE_ROWS;
    const int fullTiles  = nrows / TILE_ROWS;
    const long long logF4tot = (long long)nrows * NCLS / 4;
    const long long labF4tot = nrows / 4;
    const long long genF4tot = nrows / 2;

    if (t < NCLS) scw[t] = cw[t];

    // stage tile 'st' into buffer BN; always commits a group (possibly empty)
#define STAGE(BN, st) do {                                                     \
        if ((st) < nTiles) {                                                   \
            const unsigned sb = smem_u32(&tiles[BN]);                          \
            const float4* gL = (const float4*)logits + (long long)(st)*TILE_F4;\
            const float4* gA = (const float4*)labels + (long long)(st)*LAB_F4; \
            const float4* gG = (const float4*)gender + (long long)(st)*GEN_F4; \
            if ((st) < fullTiles) {                                            \
                cp16(sb + 16u*t, gL + t);                                      \
                if (t < TILE_F4 - BLOCK)                                       \
                    cp16(sb + 16u*(BLOCK + t), gL + BLOCK + t);                \
                else                                                           \
                    cp16(sb + 16u*(BLOCK + t), gA + (t - (TILE_F4 - BLOCK))); \
                if (t < GEN_F4)                                                \
                    cp16(sb + 16u*(TILE_F4 + LAB_F4 + t), gG + t);             \
            } else {                                                           \
                const long long lb = (long long)(st)*TILE_F4;                  \
                if (lb + t < logF4tot) cp16(sb + 16u*t, gL + t);               \
                if (t < TILE_F4 - BLOCK) {                                     \
                    if (lb + BLOCK + t < logF4tot)                             \
                        cp16(sb + 16u*(BLOCK + t), gL + BLOCK + t);            \
                } else {                                                       \
                    const int j = t - (TILE_F4 - BLOCK);                       \
                    if ((long long)(st)*LAB_F4 + j < labF4tot)                 \
                        cp16(sb + 16u*(BLOCK + t), gA + j);                    \
                }                                                              \
                if (t < GEN_F4 && (long long)(st)*GEN_F4 + t < genF4tot)       \
                    cp16(sb + 16u*(TILE_F4 + LAB_F4 + t), gG + t);             \
            }                                                                  \
        }                                                                      \
        cp_commit();                                                           \
    } while (0)

#define COMPUTE(B) do {                                                        \
        const int grow = tile * TILE_ROWS + t;                                 \
        if (grow < nrows) {                                                    \
            const Tile& tb = tiles[B];                                         \
            const float* x = tb.lg + t * NCLS;                                 \
            const float x0 = x[0], x1 = x[1], x2 = x[2], x3 = x[3],            \
                        x4 = x[4], x5 = x[5], x6 = x[6];                       \
            const float mA = fmaxf(x1, x4);                                    \
            const float mB = fmaxf(x0, fmaxf(x3, x6));                         \
            const float mC = fmaxf(x2, x5);                                    \
            const float mall = fmaxf(mA, fmaxf(mB, mC));                       \
            const int  lb = tb.lab[t];                                         \
            const int2 g  = tb.gen[t];                                         \
            const int gidx = (g.x << 1) | g.y;                                 \
            const float mval = (gidx == 0) ? mA : ((gidx == 3) ? mC : mB);     \
            const float pen  = (mall > mval) ? 5.0f : 0.0f;                    \
            const float e01 = __expf(x0) + __expf(x1);                         \
            const float e23 = __expf(x2) + __expf(x3);                         \
            const float e45 = __expf(x4) + __expf(x5);                         \
            const float sum = (e01 + e23) + (e45 + __expf(x6));                \
            local += scw[lb] * (__logf(sum) - x[lb]) + pen;                    \
        }                                                                      \
    } while (0)

    // stage tile+2G into BN; wait until tile's group done (2 newer pending);
    // sync for cross-thread cp.async visibility; compute; sync (WAR before
    // next iteration restages the just-computed buffer).
#define BODY(B, BN)                                                            \
        STAGE(BN, tile + 2 * G);                                               \
        cp_wait<2>();                                                          \
        __syncthreads();                                                       \
        COMPUTE(B);                                                            \
        tile += G;                                                             \
        if (tile >= nTiles) break;                                             \
        __syncthreads();

    float local = 0.0f;
    int tile = blockIdx.x;       // grid <= nTiles, so always valid

    STAGE(0, tile);              // prefetch depth 2
    STAGE(1, tile + G);

    while (true) {
        BODY(0, 2)
        BODY(1, 0)
        BODY(2, 1)
    }
#undef BODY
#undef COMPUTE
#undef STAGE

    // ---- block reduction ----
    #pragma unroll
    for (int off = 16; off > 0; off >>= 1)
        local += __shfl_down_sync(0xffffffffu, local, off);

    __shared__ float swarp[BLOCK / 32];
    const int lane = t & 31;
    const int wid  = t >> 5;
    if (lane == 0) swarp[wid] = local;
    __syncthreads();

    if (wid == 0) {
        float b = (lane < BLOCK / 32) ? swarp[lane] : 0.0f;
        #pragma unroll
        for (int off = 8; off > 0; off >>= 1)
            b += __shfl_down_sync(0xffffffffu, b, off);
        if (lane == 0) {
            atomicAdd(&g_accum, (double)b);
            __threadfence();
            unsigned int ticket = atomicAdd(&g_count, 1u);
            if (ticket == gridDim.x - 1) {
                out[0] = (float)(g_accum / (double)nrows);
                g_accum = 0.0;
                g_count = 0u;
            }
        }
    }
}

extern "C" void kernel_launch(void* const* d_in, const int* in_sizes, int n_in,
                              void* d_out, int out_size)
{
    const float* logits = (const float*)d_in[0];
    const float* cw     = (const float*)d_in[1];
    const int*   labels = (const int*)d_in[2];
    const int*   gender = (const int*)d_in[3];
    float* out = (float*)d_out;

    const int nrows  = in_sizes[0] / NCLS;
    const int nTiles = (nrows + TILE_ROWS - 1) / TILE_ROWS;
    const int grid   = nTiles < GRID_BLOCKS ? nTiles : GRID_BLOCKS;

    const size_t shmem = 3 * sizeof(Tile);   // 61440 B
    cudaFuncSetAttribute(gender_ce_kernel,
                         cudaFuncAttributeMaxDynamicSharedMemorySize, (int)shmem);

    gender_ce_kernel<<<grid, BLOCK, shmem>>>(logits, cw, labels, gender, out, nrows);
}

// round 9
// speedup vs baseline: 1.0691x; 1.0691x over previous
#include <cuda_runtime.h>
#include <cuda_bf16.h>

// Fused GenderAwareCrossEntropyLoss.
// All inputs (logits+labels+gender) staged via cp.async into ONE packed tile,
// 2-buffer ring, depth-1 prefetch, 100%-occupancy budget (41KB smem, 32 regs).
// d_in[0] logits f32 [N,7]; d_in[1] class_weights f32 [7];
// d_in[2] labels i32 [N];  d_in[3] gender i32 [N,2].
// d_out f32[1] = mean(weighted CE + gender penalty).

#define NCLS 7
#define BLOCK 512
#define TILE_ROWS 512
#define LOG_F4 896                       // logits float4 per tile
#define LAB_F4 128                       // labels float4 per tile
#define GEN_F4 256                       // gender float4 per tile
#define GRID_BLOCKS (148 * 4)

struct Tile {                             // 14336 + 2048 + 4096 = 20480 B
    float lg[TILE_ROWS * NCLS];
    int   lab[TILE_ROWS];
    int2  gen[TILE_ROWS];
};

__device__ double       g_accum = 0.0;
__device__ unsigned int g_count = 0u;

__device__ __forceinline__ unsigned smem_u32(const void* p) {
    return (unsigned)__cvta_generic_to_shared(p);
}
__device__ __forceinline__ void cp16(unsigned dst, const void* src) {
    asm volatile("cp.async.cg.shared.global [%0], [%1], 16;\n" :: "r"(dst), "l"(src));
}
__device__ __forceinline__ void cp_commit() {
    asm volatile("cp.async.commit_group;\n" ::: "memory");
}
template <int N>
__device__ __forceinline__ void cp_wait() {
    asm volatile("cp.async.wait_group %0;\n" :: "n"(N) : "memory");
}

__global__ void __launch_bounds__(BLOCK, 4)
gender_ce_kernel(const float* __restrict__ logits,
                 const float* __restrict__ cw,
                 const int*   __restrict__ labels,
                 const int*   __restrict__ gender,
                 float* __restrict__ out,
                 int nrows)
{
    __shared__ Tile tiles[2];            // 40 KB
    __shared__ float scw[8];

    const int t          = threadIdx.x;
    const int G          = gridDim.x;
    const int nTiles     = (nrows + TILE_ROWS - 1) / TILE_ROWS;
    const int fullTiles  = nrows / TILE_ROWS;
    // all f4 indices fit in int (nrows*7/4 = 7e6 << 2^31)
    const int logF4tot = nrows / 4 * NCLS;
    const int labF4tot = nrows / 4;
    const int genF4tot = nrows / 2;

    if (t < NCLS) scw[t] = cw[t];

    // stage tile 'st' into buffer BN; always commits a group
#define STAGE(BN, st) do {                                                     \
        const unsigned sb = smem_u32(&tiles[BN]);                              \
        const float4* gL = (const float4*)logits + (st) * LOG_F4;              \
        if ((st) < fullTiles) {                                                \
            cp16(sb + 16u * t, gL + t);                                        \
            if (t < LOG_F4 - BLOCK)                                            \
                cp16(sb + 16u * (BLOCK + t), gL + BLOCK + t);                  \
            else                                                               \
                cp16(sb + 16u * (BLOCK + t),                                   \
                     (const float4*)labels + (st) * LAB_F4 + (t - (LOG_F4 - BLOCK))); \
            if (t < GEN_F4)                                                    \
                cp16(sb + 16u * (LOG_F4 + LAB_F4 + t),                         \
                     (const float4*)gender + (st) * GEN_F4 + t);               \
        } else if ((st) < nTiles) {                                            \
            const int lbase = (st) * LOG_F4;                                   \
            if (lbase + t < logF4tot) cp16(sb + 16u * t, gL + t);              \
            if (t < LOG_F4 - BLOCK) {                                          \
                if (lbase + BLOCK + t < logF4tot)                              \
                    cp16(sb + 16u * (BLOCK + t), gL + BLOCK + t);              \
            } else {                                                           \
                const int j = t - (LOG_F4 - BLOCK);                            \
                if ((st) * LAB_F4 + j < labF4tot)                              \
                    cp16(sb + 16u * (BLOCK + t),                               \
                         (const float4*)labels + (st) * LAB_F4 + j);           \
            }                                                                  \
            if (t < GEN_F4 && (st) * GEN_F4 + t < genF4tot)                    \
                cp16(sb + 16u * (LOG_F4 + LAB_F4 + t),                         \
                     (const float4*)gender + (st) * GEN_F4 + t);               \
        }                                                                      \
        cp_commit();                                                           \
    } while (0)

#define COMPUTE(B) do {                                                        \
        const int grow = tile * TILE_ROWS + t;                                 \
        if (grow < nrows) {                                                    \
            const Tile& tb = tiles[B];                                         \
            const float* x = tb.lg + t * NCLS;                                 \
            const float x0 = x[0], x1 = x[1], x2 = x[2], x3 = x[3],            \
                        x4 = x[4], x5 = x[5], x6 = x[6];                       \
            const float mA = fmaxf(x1, x4);                                    \
            const float mB = fmaxf(x0, fmaxf(x3, x6));                         \
            const float mC = fmaxf(x2, x5);                                    \
            const float mall = fmaxf(mA, fmaxf(mB, mC));                       \
            const int  lb = tb.lab[t];                                         \
            const int2 g  = tb.gen[t];                                         \
            const int gidx = (g.x << 1) | g.y;                                 \
            const float mval = (gidx == 0) ? mA : ((gidx == 3) ? mC : mB);     \
            const float pen  = (mall > mval) ? 5.0f : 0.0f;                    \
            const float e01 = __expf(x0) + __expf(x1);                         \
            const float e23 = __expf(x2) + __expf(x3);                         \
            const float e45 = __expf(x4) + __expf(x5);                         \
            const float sum = (e01 + e23) + (e45 + __expf(x6));                \
            local += scw[lb] * (__logf(sum) - x[lb]) + pen;                    \
        }                                                                      \
    } while (0)

    // stage tile+G into the other buffer; wait for current; sync; compute;
    // sync (WAR: next iteration restages the buffer just computed).
#define BODY(B)                                                                \
        STAGE(B ^ 1, tile + G);                                                \
        cp_wait<1>();                                                          \
        __syncthreads();                                                       \
        COMPUTE(B);                                                            \
        tile += G;                                                             \
        if (tile >= nTiles) break;                                             \
        __syncthreads();

    float local = 0.0f;
    int tile = blockIdx.x;               // grid <= nTiles, always valid

    STAGE(0, tile);

    while (true) {
        BODY(0)
        BODY(1)
    }
#undef BODY
#undef COMPUTE
#undef STAGE

    // ---- block reduction ----
    #pragma unroll
    for (int off = 16; off > 0; off >>= 1)
        local += __shfl_down_sync(0xffffffffu, local, off);

    __shared__ float swarp[BLOCK / 32];
    const int lane = t & 31;
    const int wid  = t >> 5;
    if (lane == 0) swarp[wid] = local;
    __syncthreads();

    if (wid == 0) {
        float b = (lane < BLOCK / 32) ? swarp[lane] : 0.0f;
        #pragma unroll
        for (int off = 8; off > 0; off >>= 1)
            b += __shfl_down_sync(0xffffffffu, b, off);
        if (lane == 0) {
            atomicAdd(&g_accum, (double)b);
            __threadfence();
            unsigned int ticket = atomicAdd(&g_count, 1u);
            if (ticket == gridDim.x - 1) {
                out[0] = (float)(g_accum / (double)nrows);
                g_accum = 0.0;
                g_count = 0u;
            }
        }
    }
}

extern "C" void kernel_launch(void* const* d_in, const int* in_sizes, int n_in,
                              void* d_out, int out_size)
{
    const float* logits = (const float*)d_in[0];
    const float* cw     = (const float*)d_in[1];
    const int*   labels = (const int*)d_in[2];
    const int*   gender = (const int*)d_in[3];
    float* out = (float*)d_out;

    const int nrows  = in_sizes[0] / NCLS;
    const int nTiles = (nrows + TILE_ROWS - 1) / TILE_ROWS;
    const int grid   = nTiles < GRID_BLOCKS ? nTiles : GRID_BLOCKS;

    gender_ce_kernel<<<grid, BLOCK>>>(logits, cw, labels, gender, out, nrows);
}